// round 1
// baseline (speedup 1.0000x reference)
#include <cuda_runtime.h>
#include <math.h>

#define NN   40000
#define EE   640000
#define HIDN 128

// ------------------------- scratch (no allocations allowed) -----------------
__device__ __align__(16) float g_h[NN * HIDN];     // node state
__device__ __align__(16) float g_feat[NN * HIDN];  // GAT fc output
__device__ __align__(16) float g_gru[NN * 384];    // GRU gate pre-activations
__device__ __align__(16) float g_acc[NN * HIDN];   // unnormalized message sums
__device__ __align__(16) float g_el[NN * 4];
__device__ __align__(16) float g_er[NN * 4];
__device__ __align__(16) float g_emax[NN * 4];
__device__ __align__(16) float g_den[NN * 4];
__device__ __align__(16) float g_e[EE * 4];        // per-edge attention logits

// ------------------------- helpers ------------------------------------------
__device__ __forceinline__ float lrelu(float x) { return x > 0.f ? x : 0.2f * x; }

__device__ __forceinline__ void atomicMaxF(float* addr, float v) {
    if (v == 0.f) v = 0.f;  // canonicalize -0 -> +0
    if (v >= 0.f)
        atomicMax((int*)addr, __float_as_int(v));
    else
        atomicMin((unsigned int*)addr, (unsigned int)__float_as_int(v));
}

__device__ __forceinline__ void redAdd4(float* p, float a, float b, float c, float d) {
    asm volatile("red.global.add.v4.f32 [%0], {%1, %2, %3, %4};"
                 :: "l"(p), "f"(a), "f"(b), "f"(c), "f"(d) : "memory");
}

// ------------------------- fp32 SGEMM (K = 128 fixed) ------------------------
// C[M,N] = A[M,128] @ B (+ bias). TRANSB=false: B is [128,N] row-major.
// TRANSB=true:  B is [N,128] row-major (C = A @ B^T).
template <bool TRANSB>
__global__ __launch_bounds__(256) void gemm128(
    const float* __restrict__ A, const float* __restrict__ B,
    const float* __restrict__ bias, float* __restrict__ C, int M, int N)
{
    const int K = 128;
    __shared__ float As[8][128];
    __shared__ float Bs[8][132];

    int m0 = blockIdx.x * 128;
    int n0 = blockIdx.y * 128;
    int t  = threadIdx.x;
    int tr = t >> 4;      // 0..15
    int tc = t & 15;      // 0..15

    float acc[8][8];
#pragma unroll
    for (int i = 0; i < 8; i++)
#pragma unroll
        for (int j = 0; j < 8; j++) acc[i][j] = 0.f;

    int aRow = t >> 1;
    int aCol = (t & 1) * 4;
    bool aOk = (m0 + aRow) < M;
    const float* Aptr = A + (size_t)(m0 + aRow) * K + aCol;

    for (int k0 = 0; k0 < K; k0 += 8) {
        float4 av = make_float4(0.f, 0.f, 0.f, 0.f);
        if (aOk) av = *(const float4*)(Aptr + k0);
        As[aCol + 0][aRow] = av.x;
        As[aCol + 1][aRow] = av.y;
        As[aCol + 2][aRow] = av.z;
        As[aCol + 3][aRow] = av.w;

        if (!TRANSB) {
            int bRow = t >> 5;            // 0..7
            int bCol = (t & 31) * 4;      // 0..124
            float4 bv = *(const float4*)&B[(size_t)(k0 + bRow) * N + n0 + bCol];
            Bs[bRow][bCol + 0] = bv.x;
            Bs[bRow][bCol + 1] = bv.y;
            Bs[bRow][bCol + 2] = bv.z;
            Bs[bRow][bCol + 3] = bv.w;
        } else {
            int bn = t >> 1;              // 0..127
            int bk = (t & 1) * 4;         // 0 or 4
            float4 bv = *(const float4*)&B[(size_t)(n0 + bn) * K + k0 + bk];
            Bs[bk + 0][bn] = bv.x;
            Bs[bk + 1][bn] = bv.y;
            Bs[bk + 2][bn] = bv.z;
            Bs[bk + 3][bn] = bv.w;
        }
        __syncthreads();

#pragma unroll
        for (int kk = 0; kk < 8; kk++) {
            float ra[8], rb[8];
#pragma unroll
            for (int i = 0; i < 8; i++) ra[i] = As[kk][tr * 8 + i];
#pragma unroll
            for (int j = 0; j < 8; j++) rb[j] = Bs[kk][tc * 8 + j];
#pragma unroll
            for (int i = 0; i < 8; i++)
#pragma unroll
                for (int j = 0; j < 8; j++) acc[i][j] += ra[i] * rb[j];
        }
        __syncthreads();
    }

#pragma unroll
    for (int i = 0; i < 8; i++) {
        int m = m0 + tr * 8 + i;
        if (m < M) {
#pragma unroll
            for (int j4 = 0; j4 < 8; j4 += 4) {
                int n = n0 + tc * 8 + j4;
                float4 v;
                v.x = acc[i][j4 + 0];
                v.y = acc[i][j4 + 1];
                v.z = acc[i][j4 + 2];
                v.w = acc[i][j4 + 3];
                if (bias) {
                    v.x += bias[n + 0]; v.y += bias[n + 1];
                    v.z += bias[n + 2]; v.w += bias[n + 3];
                }
                *(float4*)&C[(size_t)m * N + n] = v;
            }
        }
    }
}

// ------------------------- GAT pieces ---------------------------------------
// el[n,h] = <feat[n,h,:], attn_l[h,:]>, er likewise. One thread per (n,h).
__global__ void lr_kernel(const float* __restrict__ al, const float* __restrict__ ar)
{
    int i = blockIdx.x * blockDim.x + threadIdx.x;
    if (i >= NN * 4) return;
    int h = i & 3;
    const float4* f = (const float4*)&g_feat[(size_t)(i >> 2) * HIDN + h * 32];
    const float4* a = (const float4*)&al[h * 32];
    const float4* b = (const float4*)&ar[h * 32];
    float l = 0.f, r = 0.f;
#pragma unroll
    for (int q = 0; q < 8; q++) {
        float4 fv = f[q], av = a[q], bv = b[q];
        l += fv.x * av.x + fv.y * av.y + fv.z * av.z + fv.w * av.w;
        r += fv.x * bv.x + fv.y * bv.y + fv.z * bv.z + fv.w * bv.w;
    }
    g_el[i] = l;
    g_er[i] = r;
}

__global__ void init_kernel()
{
    int i = blockIdx.x * blockDim.x + threadIdx.x;
    if (i < NN * HIDN) g_acc[i] = 0.f;
    if (i < NN * 4) {
        g_emax[i] = -INFINITY;
        g_den[i]  = 0.f;
    }
}

// Pass 1: per-edge logits + running max per (dst, head). One thread per edge.
__global__ void edgeA_kernel(const int* __restrict__ src, const int* __restrict__ dst)
{
    int e = blockIdx.x * blockDim.x + threadIdx.x;
    if (e >= EE) return;
    int s = src[e], d = dst[e];
    float4 l = *(const float4*)&g_el[s * 4];
    float4 r = *(const float4*)&g_er[d * 4];
    float4 v;
    v.x = lrelu(l.x + r.x);
    v.y = lrelu(l.y + r.y);
    v.z = lrelu(l.z + r.z);
    v.w = lrelu(l.w + r.w);
    *(float4*)&g_e[e * 4] = v;
    atomicMaxF(&g_emax[d * 4 + 0], v.x);
    atomicMaxF(&g_emax[d * 4 + 1], v.y);
    atomicMaxF(&g_emax[d * 4 + 2], v.z);
    atomicMaxF(&g_emax[d * 4 + 3], v.w);
}

// Pass 2: w = exp(e - max); denom += w; acc[dst] += w * feat[src].
// One warp per edge: 32 lanes x float4 cover the 128-wide feature row.
__global__ void edgeB_kernel(const int* __restrict__ src, const int* __restrict__ dst)
{
    int warp = (blockIdx.x * blockDim.x + threadIdx.x) >> 5;
    int lane = threadIdx.x & 31;
    if (warp >= EE) return;
    int s = src[warp], d = dst[warp];
    int h = lane >> 3;
    float w = __expf(g_e[warp * 4 + h] - g_emax[d * 4 + h]);
    if ((lane & 7) == 0) atomicAdd(&g_den[d * 4 + h], w);
    float4 f = *(const float4*)&g_feat[(size_t)s * HIDN + lane * 4];
    redAdd4(&g_acc[(size_t)d * HIDN + lane * 4], f.x * w, f.y * w, f.z * w, f.w * w);
}

// Epilogue: h = elu(acc/denom + h + bias)
__global__ void finalize_kernel(const float* __restrict__ bias)
{
    int i = blockIdx.x * blockDim.x + threadIdx.x;
    if (i >= NN * HIDN) return;
    int c = i & 127;
    float den = g_den[(i >> 7) * 4 + (c >> 5)];
    float v = (den > 0.f ? g_acc[i] / den : 0.f) + g_h[i] + bias[c];
    g_h[i] = v > 0.f ? v : (__expf(v) - 1.f);
}

// ------------------------- GRU ----------------------------------------------
__global__ void gru_kernel(const float* __restrict__ bhh, float* __restrict__ out)
{
    int i = blockIdx.x * blockDim.x + threadIdx.x;
    if (i >= NN * HIDN) return;
    int n = i >> 7, c = i & 127;
    const float* g = &g_gru[(size_t)n * 384];
    float r  = 1.f / (1.f + __expf(-(g[c] + bhh[c])));
    float z  = 1.f / (1.f + __expf(-(g[128 + c] + bhh[128 + c])));
    float nn = tanhf(g[256 + c] + r * bhh[256 + c]);
    out[i] = (1.f - z) * nn;
}

// ------------------------- launch -------------------------------------------
extern "C" void kernel_launch(void* const* d_in, const int* in_sizes, int n_in,
                              void* d_out, int out_size)
{
    const float* node  = (const float*)d_in[0];
    const int*   src   = (const int*)d_in[1];
    const int*   dst   = (const int*)d_in[2];
    const float* projW = (const float*)d_in[3];
    const float* projb = (const float*)d_in[4];
    const float* fcW   = (const float*)d_in[5];
    const float* attl  = (const float*)d_in[6];
    const float* attr_ = (const float*)d_in[7];
    const float* cbias = (const float*)d_in[8];
    const float* Wih   = (const float*)d_in[9];
    // d_in[10] = gru_Whh, unused (h0 == 0)
    const float* bih   = (const float*)d_in[11];
    const float* bhh   = (const float*)d_in[12];
    float* out = (float*)d_out;

    float *p_h, *p_feat, *p_gru;
    cudaGetSymbolAddress((void**)&p_h, g_h);
    cudaGetSymbolAddress((void**)&p_feat, g_feat);
    cudaGetSymbolAddress((void**)&p_gru, g_gru);

    const int MT = (NN + 127) / 128;  // 313 M-tiles

    // 1) input projection: h = node_feats @ proj_W + proj_b
    gemm128<false><<<dim3(MT, 1), 256>>>(node, projW, projb, p_h, NN, HIDN);

    // 2) 3 GAT layers
    for (int l = 0; l < 3; l++) {
        gemm128<false><<<dim3(MT, 1), 256>>>(p_h, fcW + (size_t)l * HIDN * HIDN,
                                             nullptr, p_feat, NN, HIDN);
        lr_kernel<<<(NN * 4 + 255) / 256, 256>>>(attl + l * HIDN, attr_ + l * HIDN);
        init_kernel<<<(NN * HIDN + 255) / 256, 256>>>();
        edgeA_kernel<<<(EE + 255) / 256, 256>>>(src, dst);
        edgeB_kernel<<<EE / 8, 256>>>(src, dst);
        finalize_kernel<<<(NN * HIDN + 255) / 256, 256>>>(cbias + l * HIDN);
    }

    // 3) 2 GRU timesteps (Whh term vanishes; h0 = 0)
    gemm128<true><<<dim3(MT, 3), 256>>>(p_h, Wih, bih, p_gru, NN, 384);
    gru_kernel<<<(NN * HIDN + 255) / 256, 256>>>(bhh, p_h);

    gemm128<true><<<dim3(MT, 3), 256>>>(p_h, Wih, bih, p_gru, NN, 384);
    gru_kernel<<<(NN * HIDN + 255) / 256, 256>>>(bhh, out);
}